// round 3
// baseline (speedup 1.0000x reference)
#include <cuda_runtime.h>
#include <math.h>

// Problem constants (fixed by the dataset)
#define BATCH   512
#define IN_DIM  128
#define OUT_DIM 128
#define NFEAT   9                  // silu + 8 basis functions
#define IPB     4                  // input dims per block (k-split granularity)
#define KC      (IPB * NFEAT)      // 36 k per block
#define SPLITS  (IN_DIM / IPB)     // 32 k-splits
#define BM      64                 // batch rows per block
#define MT      (BATCH / BM)       // 8 m-tiles
#define FS_STR  68                 // padded Fs row stride (floats)
#define WS_STR  132                // padded Ws row stride (floats)

// Scratch (device global — no allocation in kernel_launch)
__device__ float g_P[SPLITS * BATCH * OUT_DIM];   // split-K partials (8.4 MB)

// ---------------------------------------------------------------------------
// f32x2 packed helpers (sm_103a FFMA2 — ptxas never emits this from C++)
// ---------------------------------------------------------------------------
__device__ __forceinline__ unsigned long long dup_f32x2(float v) {
    unsigned long long d;
    unsigned int u = __float_as_uint(v);
    asm("mov.b64 %0, {%1, %1};" : "=l"(d) : "r"(u));
    return d;
}
__device__ __forceinline__ void ffma2(unsigned long long& acc,
                                      unsigned long long a,
                                      unsigned long long b) {
    asm("fma.rn.f32x2 %0, %1, %2, %0;" : "+l"(acc) : "l"(a), "l"(b));
}

// ---------------------------------------------------------------------------
// Fused kernel: build Fs (spline features) + Ws (weights) in smem from the raw
// inputs, then run the f32x2 register-tiled GEMM for this (m-tile, k-split).
// grid = (8, 32) = 256 blocks, 128 threads, 2 blocks/SM.
// ---------------------------------------------------------------------------
__global__ void __launch_bounds__(128, 2)
fused_kernel(const float* __restrict__ x,
             const float* __restrict__ grid,
             const float* __restrict__ coef,
             const float* __restrict__ sb,
             const float* __restrict__ ss,
             const float* __restrict__ mask) {
    __shared__ float Fs[KC * FS_STR];   //  9.8 KB, [k][m] padded
    __shared__ float Ws[KC * WS_STR];   // 19.0 KB, [k][o] padded

    const int t  = threadIdx.x;
    const int m0 = blockIdx.x * BM;
    const int i0 = blockIdx.y * IPB;

    // ---- uniform extended knot vector (division-free) ----
    const float g0 = grid[0];
    const float g5 = grid[5];
    const float step = (g5 - g0) * 0.2f;
    const float inv1 = __frcp_rn(step);
    const float invr[3] = { inv1, 0.5f * inv1, inv1 * (1.0f / 3.0f) };

    float tk[12];
    tk[0]  = g0 - step * 3.0f;
    tk[1]  = g0 - step * 2.0f;
    tk[2]  = g0 - step;
    tk[3]  = g0;
    tk[4]  = grid[1];
    tk[5]  = grid[2];
    tk[6]  = grid[3];
    tk[7]  = grid[4];
    tk[8]  = g5;
    tk[9]  = g5 + step;
    tk[10] = g5 + step * 2.0f;
    tk[11] = g5 + step * 3.0f;

    // ---- Fs build: 64 n x 4 i = 256 x-values, 2 per thread ----
#pragma unroll
    for (int p = 0; p < 2; p++) {
        const int il = t & 3;
        const int nl = (t >> 2) + p * 32;
        const float xv = __ldg(&x[(m0 + nl) * IN_DIM + i0 + il]);

        const float sig  = __frcp_rn(1.0f + __expf(-xv));
        const float silu = xv * sig;

        float B[11];
#pragma unroll
        for (int m = 0; m < 11; m++)
            B[m] = (xv >= tk[m] && xv < tk[m + 1]) ? 1.0f : 0.0f;
#pragma unroll
        for (int r = 1; r <= 3; r++) {
            const float iv = invr[r - 1];
#pragma unroll
            for (int m = 0; m < 11 - r; m++) {
                float alpha = (xv - tk[m]) * iv;
                float beta  = (tk[m + r + 1] - xv) * iv;
                B[m] = alpha * B[m] + beta * B[m + 1];
            }
        }

        const int kb = il * NFEAT;
        Fs[kb * FS_STR + nl] = silu;
#pragma unroll
        for (int j = 0; j < 8; j++)
            Fs[(kb + 1 + j) * FS_STR + nl] = B[j];
    }

    // ---- Ws build: warp handles 32 o's; per o, 32 lanes hold coef[4i][8j] ----
    {
        const int lane = t & 31;
        const int il   = lane >> 3;      // which of the 4 i's this lane's coef is
        const int j    = lane & 7;       // coef index within i
        const int obase = (t >> 5) * 32; // warp's o range

#pragma unroll 4
        for (int oi = 0; oi < 32; oi++) {
            const int o     = obase + oi;
            const int sbase = o * IN_DIM + i0;

            // 32 consecutive coef floats (one 128B line per warp load)
            const float cf = __ldg(&coef[sbase * 8 + lane]);

            float mk0 = 0.f, sb0 = 0.f, ss0 = 0.f;
            if (lane < IPB) {
                mk0 = __ldg(&mask[sbase + lane]);
                sb0 = __ldg(&sb[sbase + lane]);
                ss0 = __ldg(&ss[sbase + lane]);
            }
            const float mk  = __shfl_sync(0xffffffffu, mk0, il);
            const float sbv = __shfl_sync(0xffffffffu, sb0, il);
            const float ssv = __shfl_sync(0xffffffffu, ss0, il);

            Ws[(il * NFEAT + 1 + j) * WS_STR + o] = mk * ssv * cf;
            if (j == 0)
                Ws[(il * NFEAT) * WS_STR + o] = mk * sbv;
        }
    }

    __syncthreads();

    // ---- GEMM: 8m x 8o register tile, packed f32x2 ----
    const int tm8 = (t >> 4) * 8;       // 0..56
    const int to8 = (t & 15) * 8;       // 0..120

    unsigned long long acc[8][4];
#pragma unroll
    for (int a = 0; a < 8; a++)
#pragma unroll
        for (int b = 0; b < 4; b++) acc[a][b] = 0ULL;

#pragma unroll 4
    for (int k = 0; k < KC; k++) {
        const float4 fa = *(const float4*)&Fs[k * FS_STR + tm8];
        const float4 fb = *(const float4*)&Fs[k * FS_STR + tm8 + 4];
        const ulonglong2 wa = *(const ulonglong2*)&Ws[k * WS_STR + to8];
        const ulonglong2 wb = *(const ulonglong2*)&Ws[k * WS_STR + to8 + 4];

        unsigned long long fd[8];
        fd[0] = dup_f32x2(fa.x); fd[1] = dup_f32x2(fa.y);
        fd[2] = dup_f32x2(fa.z); fd[3] = dup_f32x2(fa.w);
        fd[4] = dup_f32x2(fb.x); fd[5] = dup_f32x2(fb.y);
        fd[6] = dup_f32x2(fb.z); fd[7] = dup_f32x2(fb.w);

#pragma unroll
        for (int a = 0; a < 8; a++) {
            ffma2(acc[a][0], fd[a], wa.x);
            ffma2(acc[a][1], fd[a], wa.y);
            ffma2(acc[a][2], fd[a], wb.x);
            ffma2(acc[a][3], fd[a], wb.y);
        }
    }

    float* P = &g_P[blockIdx.y * (BATCH * OUT_DIM)];
#pragma unroll
    for (int a = 0; a < 8; a++) {
        const int row = m0 + tm8 + a;
        ulonglong2 v0; v0.x = acc[a][0]; v0.y = acc[a][1];
        ulonglong2 v1; v1.x = acc[a][2]; v1.y = acc[a][3];
        *(ulonglong2*)&P[row * OUT_DIM + to8]     = v0;
        *(ulonglong2*)&P[row * OUT_DIM + to8 + 4] = v1;
    }
}

// ---------------------------------------------------------------------------
// Reduce: sum the 32 split-K partials into the final output (deterministic).
// 16384 threads, float4 each; fully coalesced.
// ---------------------------------------------------------------------------
__global__ void reduce_kernel(float* __restrict__ out) {
    const int t4 = blockIdx.x * blockDim.x + threadIdx.x;
    float4 s = make_float4(0.f, 0.f, 0.f, 0.f);
#pragma unroll
    for (int q = 0; q < SPLITS; q++) {
        const float4 v = *(const float4*)&g_P[q * (BATCH * OUT_DIM) + t4 * 4];
        s.x += v.x; s.y += v.y; s.z += v.z; s.w += v.w;
    }
    *(float4*)&out[t4 * 4] = s;
}

// ---------------------------------------------------------------------------
extern "C" void kernel_launch(void* const* d_in, const int* in_sizes, int n_in,
                              void* d_out, int out_size) {
    const float* x    = (const float*)d_in[0];
    const float* grid = (const float*)d_in[1];
    const float* coef = (const float*)d_in[2];
    const float* sb   = (const float*)d_in[3];
    const float* ss   = (const float*)d_in[4];
    const float* mask = (const float*)d_in[5];
    float* out = (float*)d_out;

    fused_kernel<<<dim3(MT, SPLITS), 128>>>(x, grid, coef, sb, ss, mask);
    reduce_kernel<<<64, 256>>>(out);
}

// round 4
// speedup vs baseline: 1.1380x; 1.1380x over previous
#include <cuda_runtime.h>
#include <math.h>

// Problem constants (fixed by the dataset)
#define BATCH   512
#define IN_DIM  128
#define OUT_DIM 128
#define NFEAT   9                  // silu + 8 basis functions
#define IPB     8                  // input dims per block (k-split granularity)
#define KC      (IPB * NFEAT)      // 72 k per block
#define SPLITS  (IN_DIM / IPB)     // 16 k-splits
#define BM      64                 // batch rows per block
#define MT      (BATCH / BM)       // 8 m-tiles
#define FS_STR  68                 // padded Fs row stride (floats)
#define WS_STR  132                // padded Ws row stride (floats)
#define NOUT    (BATCH * OUT_DIM)  // 65536

// Scratch (device global — no allocation in kernel_launch)
__device__ float g_P[SPLITS * NOUT];   // split-K partials (4.2 MB)

// ---------------------------------------------------------------------------
// f32x2 packed helpers (sm_103a FFMA2 — ptxas never emits this from C++)
// ---------------------------------------------------------------------------
__device__ __forceinline__ unsigned long long dup_f32x2(float v) {
    unsigned long long d;
    unsigned int u = __float_as_uint(v);
    asm("mov.b64 %0, {%1, %1};" : "=l"(d) : "r"(u));
    return d;
}
__device__ __forceinline__ void ffma2(unsigned long long& acc,
                                      unsigned long long a,
                                      unsigned long long b) {
    asm("fma.rn.f32x2 %0, %1, %2, %0;" : "+l"(acc) : "l"(a), "l"(b));
}

// ---------------------------------------------------------------------------
// Fused kernel: build Fs (spline features) + Ws (weights) in smem, then the
// f32x2 register-tiled GEMM for this (m-tile, k-split).
// grid = (8, 16) = 128 blocks, 256 threads (8 warps) each.
// ---------------------------------------------------------------------------
__global__ void __launch_bounds__(256, 1)
fused_kernel(const float* __restrict__ x,
             const float* __restrict__ grid,
             const float* __restrict__ coef,
             const float* __restrict__ sb,
             const float* __restrict__ ss,
             const float* __restrict__ mask) {
    __shared__ float Fs[KC * FS_STR];   // 19.1 KB, [k][m] padded
    __shared__ float Ws[KC * WS_STR];   // 37.1 KB, [k][o] padded

    const int t  = threadIdx.x;
    const int m0 = blockIdx.x * BM;
    const int i0 = blockIdx.y * IPB;

    // ---- uniform extended knot vector (division-free) ----
    const float g0 = grid[0];
    const float g5 = grid[5];
    const float step = (g5 - g0) * 0.2f;
    const float inv1 = __frcp_rn(step);
    const float invr[3] = { inv1, 0.5f * inv1, inv1 * (1.0f / 3.0f) };

    float tk[12];
    tk[0]  = g0 - step * 3.0f;
    tk[1]  = g0 - step * 2.0f;
    tk[2]  = g0 - step;
    tk[3]  = g0;
    tk[4]  = grid[1];
    tk[5]  = grid[2];
    tk[6]  = grid[3];
    tk[7]  = grid[4];
    tk[8]  = g5;
    tk[9]  = g5 + step;
    tk[10] = g5 + step * 2.0f;
    tk[11] = g5 + step * 3.0f;

    // ---- Fs build: 64 n x 8 i = 512 x-values, 2 per thread ----
#pragma unroll
    for (int p = 0; p < 2; p++) {
        const int il = t & 7;
        const int nl = (t >> 3) + p * 32;
        const float xv = __ldg(&x[(m0 + nl) * IN_DIM + i0 + il]);

        const float sig  = __frcp_rn(1.0f + __expf(-xv));
        const float silu = xv * sig;

        float B[11];
#pragma unroll
        for (int m = 0; m < 11; m++)
            B[m] = (xv >= tk[m] && xv < tk[m + 1]) ? 1.0f : 0.0f;
#pragma unroll
        for (int r = 1; r <= 3; r++) {
            const float iv = invr[r - 1];
#pragma unroll
            for (int m = 0; m < 11 - r; m++) {
                float alpha = (xv - tk[m]) * iv;
                float beta  = (tk[m + r + 1] - xv) * iv;
                B[m] = alpha * B[m] + beta * B[m + 1];
            }
        }

        const int kb = il * NFEAT;
        Fs[kb * FS_STR + nl] = silu;
#pragma unroll
        for (int j = 0; j < 8; j++)
            Fs[(kb + 1 + j) * FS_STR + nl] = B[j];
    }

    // ---- Ws build: 128 o x 8 i = 1024 (o,i) pairs, 4 per thread ----
#pragma unroll
    for (int q = 0; q < 4; q++) {
        const int p = t + 256 * q;
        const int o = p >> 3;
        const int i = p & 7;
        const int s = o * IN_DIM + i0 + i;

        const float4 c0 = __ldg((const float4*)&coef[s * 8]);
        const float4 c1 = __ldg((const float4*)&coef[s * 8 + 4]);
        const float mk  = __ldg(&mask[s]);
        const float wb  = mk * __ldg(&sb[s]);
        const float ws  = mk * __ldg(&ss[s]);

        const int kb = i * NFEAT;
        Ws[kb * WS_STR + o]       = wb;
        Ws[(kb + 1) * WS_STR + o] = ws * c0.x;
        Ws[(kb + 2) * WS_STR + o] = ws * c0.y;
        Ws[(kb + 3) * WS_STR + o] = ws * c0.z;
        Ws[(kb + 4) * WS_STR + o] = ws * c0.w;
        Ws[(kb + 5) * WS_STR + o] = ws * c1.x;
        Ws[(kb + 6) * WS_STR + o] = ws * c1.y;
        Ws[(kb + 7) * WS_STR + o] = ws * c1.z;
        Ws[(kb + 8) * WS_STR + o] = ws * c1.w;
    }

    __syncthreads();

    // ---- GEMM: 4m x 8o register tile per thread, packed f32x2 ----
    const int tm4 = (t >> 4) * 4;       // 0..60
    const int to8 = (t & 15) * 8;       // 0..120

    unsigned long long acc[4][4];       // 4 m-rows x 4 o-pairs
#pragma unroll
    for (int a = 0; a < 4; a++)
#pragma unroll
        for (int b = 0; b < 4; b++) acc[a][b] = 0ULL;

#pragma unroll 6
    for (int k = 0; k < KC; k++) {
        const float4 fa = *(const float4*)&Fs[k * FS_STR + tm4];
        const ulonglong2 wa = *(const ulonglong2*)&Ws[k * WS_STR + to8];
        const ulonglong2 wb = *(const ulonglong2*)&Ws[k * WS_STR + to8 + 4];

        unsigned long long fd[4];
        fd[0] = dup_f32x2(fa.x); fd[1] = dup_f32x2(fa.y);
        fd[2] = dup_f32x2(fa.z); fd[3] = dup_f32x2(fa.w);

#pragma unroll
        for (int a = 0; a < 4; a++) {
            ffma2(acc[a][0], fd[a], wa.x);
            ffma2(acc[a][1], fd[a], wa.y);
            ffma2(acc[a][2], fd[a], wb.x);
            ffma2(acc[a][3], fd[a], wb.y);
        }
    }

    float* P = &g_P[blockIdx.y * NOUT];
#pragma unroll
    for (int a = 0; a < 4; a++) {
        const int row = m0 + tm4 + a;
        ulonglong2 v0; v0.x = acc[a][0]; v0.y = acc[a][1];
        ulonglong2 v1; v1.x = acc[a][2]; v1.y = acc[a][3];
        *(ulonglong2*)&P[row * OUT_DIM + to8]     = v0;
        *(ulonglong2*)&P[row * OUT_DIM + to8 + 4] = v1;
    }
}

// ---------------------------------------------------------------------------
// Reduce: 65536 threads, one output each, 16 independent L2 reads (MLP=16).
// Deterministic (fixed ascending-split order).
// ---------------------------------------------------------------------------
__global__ void __launch_bounds__(256) reduce_kernel(float* __restrict__ out) {
    const int t = blockIdx.x * blockDim.x + threadIdx.x;
    float v[SPLITS];
#pragma unroll
    for (int q = 0; q < SPLITS; q++)
        v[q] = g_P[q * NOUT + t];
    float s = 0.0f;
#pragma unroll
    for (int q = 0; q < SPLITS; q++)
        s += v[q];
    out[t] = s;
}

// ---------------------------------------------------------------------------
extern "C" void kernel_launch(void* const* d_in, const int* in_sizes, int n_in,
                              void* d_out, int out_size) {
    const float* x    = (const float*)d_in[0];
    const float* grid = (const float*)d_in[1];
    const float* coef = (const float*)d_in[2];
    const float* sb   = (const float*)d_in[3];
    const float* ss   = (const float*)d_in[4];
    const float* mask = (const float*)d_in[5];
    float* out = (float*)d_out;

    fused_kernel<<<dim3(MT, SPLITS), 256>>>(x, grid, coef, sb, ss, mask);
    reduce_kernel<<<NOUT / 256, 256>>>(out);
}

// round 5
// speedup vs baseline: 1.1577x; 1.0173x over previous
#include <cuda_runtime.h>
#include <math.h>

// Problem constants (fixed by the dataset)
#define BATCH   512
#define IN_DIM  128
#define OUT_DIM 128
#define NFEAT   9                  // silu + 8 basis functions
#define IPB     8                  // input dims per block (k-split granularity)
#define KC      (IPB * NFEAT)      // 72 k per block
#define SPLITS  (IN_DIM / IPB)     // 16 k-splits
#define BM      64                 // batch rows per block
#define MT      (BATCH / BM)       // 8 m-tiles
#define NBLK    (MT * SPLITS)      // 128 blocks (single wave on 148 SMs)
#define FS_STR  68                 // padded Fs row stride (floats)
#define WS_STR  132                // padded Ws row stride (floats)
#define NOUT    (BATCH * OUT_DIM)  // 65536

// Scratch (device globals — no allocation in kernel_launch)
__device__ float        g_P[SPLITS * NOUT];  // split-K partials (4.2 MB)
__device__ unsigned int g_bar;               // monotonic barrier ticket counter

// ---------------------------------------------------------------------------
// f32x2 packed helpers (sm_103a FFMA2 — ptxas never emits this from C++)
// ---------------------------------------------------------------------------
__device__ __forceinline__ unsigned long long dup_f32x2(float v) {
    unsigned long long d;
    unsigned int u = __float_as_uint(v);
    asm("mov.b64 %0, {%1, %1};" : "=l"(d) : "r"(u));
    return d;
}
__device__ __forceinline__ void ffma2(unsigned long long& acc,
                                      unsigned long long a,
                                      unsigned long long b) {
    asm("fma.rn.f32x2 %0, %1, %2, %0;" : "+l"(acc) : "l"(a), "l"(b));
}

// ---------------------------------------------------------------------------
// Single persistent kernel:
//   phase 1: build Fs/Ws in smem, f32x2 register-tiled GEMM -> partials in L2
//   grid barrier (monotonic ticket; replay-safe, no reset needed)
//   phase 2: all 32768 threads reduce the L2-warm partials -> out
// grid = (8, 16) = 128 blocks, 256 threads.
// ---------------------------------------------------------------------------
__global__ void __launch_bounds__(256, 1)
fused_kernel(const float* __restrict__ x,
             const float* __restrict__ grid,
             const float* __restrict__ coef,
             const float* __restrict__ sb,
             const float* __restrict__ ss,
             const float* __restrict__ mask,
             float* __restrict__ out) {
    __shared__ float Fs[KC * FS_STR];   // 19.1 KB, [k][m] padded
    __shared__ float Ws[KC * WS_STR];   // 37.1 KB, [k][o] padded

    const int t  = threadIdx.x;
    const int m0 = blockIdx.x * BM;
    const int i0 = blockIdx.y * IPB;

    // ---- uniform extended knot vector (division-free) ----
    const float g0 = grid[0];
    const float g5 = grid[5];
    const float step = (g5 - g0) * 0.2f;
    const float inv1 = __frcp_rn(step);
    const float invr[3] = { inv1, 0.5f * inv1, inv1 * (1.0f / 3.0f) };

    float tk[12];
    tk[0]  = g0 - step * 3.0f;
    tk[1]  = g0 - step * 2.0f;
    tk[2]  = g0 - step;
    tk[3]  = g0;
    tk[4]  = grid[1];
    tk[5]  = grid[2];
    tk[6]  = grid[3];
    tk[7]  = grid[4];
    tk[8]  = g5;
    tk[9]  = g5 + step;
    tk[10] = g5 + step * 2.0f;
    tk[11] = g5 + step * 3.0f;

    // ---- Fs build: 64 n x 8 i = 512 x-values, 2 per thread ----
#pragma unroll
    for (int p = 0; p < 2; p++) {
        const int il = t & 7;
        const int nl = (t >> 3) + p * 32;
        const float xv = __ldg(&x[(m0 + nl) * IN_DIM + i0 + il]);

        const float sig  = __frcp_rn(1.0f + __expf(-xv));
        const float silu = xv * sig;

        float B[11];
#pragma unroll
        for (int m = 0; m < 11; m++)
            B[m] = (xv >= tk[m] && xv < tk[m + 1]) ? 1.0f : 0.0f;
#pragma unroll
        for (int r = 1; r <= 3; r++) {
            const float iv = invr[r - 1];
#pragma unroll
            for (int m = 0; m < 11 - r; m++) {
                float alpha = (xv - tk[m]) * iv;
                float beta  = (tk[m + r + 1] - xv) * iv;
                B[m] = alpha * B[m] + beta * B[m + 1];
            }
        }

        const int kb = il * NFEAT;
        Fs[kb * FS_STR + nl] = silu;
#pragma unroll
        for (int j = 0; j < 8; j++)
            Fs[(kb + 1 + j) * FS_STR + nl] = B[j];
    }

    // ---- Ws build: 128 o x 8 i = 1024 (o,i) pairs, 4 per thread ----
#pragma unroll
    for (int q = 0; q < 4; q++) {
        const int p = t + 256 * q;
        const int o = p >> 3;
        const int i = p & 7;
        const int s = o * IN_DIM + i0 + i;

        const float4 c0 = __ldg((const float4*)&coef[s * 8]);
        const float4 c1 = __ldg((const float4*)&coef[s * 8 + 4]);
        const float mk  = __ldg(&mask[s]);
        const float wb  = mk * __ldg(&sb[s]);
        const float ws  = mk * __ldg(&ss[s]);

        const int kb = i * NFEAT;
        Ws[kb * WS_STR + o]       = wb;
        Ws[(kb + 1) * WS_STR + o] = ws * c0.x;
        Ws[(kb + 2) * WS_STR + o] = ws * c0.y;
        Ws[(kb + 3) * WS_STR + o] = ws * c0.z;
        Ws[(kb + 4) * WS_STR + o] = ws * c0.w;
        Ws[(kb + 5) * WS_STR + o] = ws * c1.x;
        Ws[(kb + 6) * WS_STR + o] = ws * c1.y;
        Ws[(kb + 7) * WS_STR + o] = ws * c1.z;
        Ws[(kb + 8) * WS_STR + o] = ws * c1.w;
    }

    __syncthreads();

    // ---- GEMM: 4m x 8o register tile per thread, packed f32x2 ----
    const int tm4 = (t >> 4) * 4;       // 0..60
    const int to8 = (t & 15) * 8;       // 0..120

    unsigned long long acc[4][4];       // 4 m-rows x 4 o-pairs
#pragma unroll
    for (int a = 0; a < 4; a++)
#pragma unroll
        for (int b = 0; b < 4; b++) acc[a][b] = 0ULL;

#pragma unroll 6
    for (int k = 0; k < KC; k++) {
        const float4 fa = *(const float4*)&Fs[k * FS_STR + tm4];
        const ulonglong2 wa = *(const ulonglong2*)&Ws[k * WS_STR + to8];
        const ulonglong2 wb = *(const ulonglong2*)&Ws[k * WS_STR + to8 + 4];

        unsigned long long fd[4];
        fd[0] = dup_f32x2(fa.x); fd[1] = dup_f32x2(fa.y);
        fd[2] = dup_f32x2(fa.z); fd[3] = dup_f32x2(fa.w);

#pragma unroll
        for (int a = 0; a < 4; a++) {
            ffma2(acc[a][0], fd[a], wa.x);
            ffma2(acc[a][1], fd[a], wa.y);
            ffma2(acc[a][2], fd[a], wb.x);
            ffma2(acc[a][3], fd[a], wb.y);
        }
    }

    float* P = &g_P[blockIdx.y * NOUT];
#pragma unroll
    for (int a = 0; a < 4; a++) {
        const int row = m0 + tm4 + a;
        ulonglong2 v0; v0.x = acc[a][0]; v0.y = acc[a][1];
        ulonglong2 v1; v1.x = acc[a][2]; v1.y = acc[a][3];
        *(ulonglong2*)&P[row * OUT_DIM + to8]     = v0;
        *(ulonglong2*)&P[row * OUT_DIM + to8 + 4] = v1;
    }

    // ---- grid barrier (monotonic ticket; works across graph replays) ----
    __threadfence();                 // partials visible before arrival
    __syncthreads();                 // all threads in block done writing
    __shared__ unsigned int s_target;
    if (t == 0) {
        unsigned int ticket = atomicAdd(&g_bar, 1u);
        s_target = ticket - (ticket & (NBLK - 1)) + NBLK;  // epoch base + 128
    }
    __syncthreads();
    if (t == 0) {
        const unsigned int target = s_target;
        while (*(volatile unsigned int*)&g_bar < target) { }
    }
    __syncthreads();
    __threadfence();                 // acquire: order partial reads after flag

    // ---- phase 2: reduce L2-warm partials (deterministic fixed order) ----
    const int flat = blockIdx.y * MT + blockIdx.x;      // 0..127
    const int gt   = flat * 256 + t;                     // 0..32767
#pragma unroll
    for (int rep = 0; rep < 2; rep++) {
        const int idx = gt + rep * (NBLK * 256);
        float v[SPLITS];
#pragma unroll
        for (int q = 0; q < SPLITS; q++)
            v[q] = g_P[q * NOUT + idx];
        float s = 0.0f;
#pragma unroll
        for (int q = 0; q < SPLITS; q++)
            s += v[q];
        out[idx] = s;
    }
}

// ---------------------------------------------------------------------------
extern "C" void kernel_launch(void* const* d_in, const int* in_sizes, int n_in,
                              void* d_out, int out_size) {
    const float* x    = (const float*)d_in[0];
    const float* grid = (const float*)d_in[1];
    const float* coef = (const float*)d_in[2];
    const float* sb   = (const float*)d_in[3];
    const float* ss   = (const float*)d_in[4];
    const float* mask = (const float*)d_in[5];
    float* out = (float*)d_out;

    fused_kernel<<<dim3(MT, SPLITS), 256>>>(x, grid, coef, sb, ss, mask, out);
}

// round 6
// speedup vs baseline: 1.3170x; 1.1376x over previous
#include <cuda_runtime.h>
#include <math.h>

// Problem constants (fixed by the dataset)
#define BATCH   512
#define IN_DIM  128
#define OUT_DIM 128
#define NFEAT   9                  // silu + 8 basis functions
#define IPB     8                  // input dims per block (k-split granularity)
#define KC      (IPB * NFEAT)      // 72 k per block
#define SPLITS  (IN_DIM / IPB)     // 16 k-splits
#define BM      64                 // batch rows per block
#define MT      (BATCH / BM)       // 8 m-tiles
#define NBLK    (MT * SPLITS)      // 128 blocks (single wave on 148 SMs)
#define NTHR    512
#define FS_STR  68                 // padded Fs row stride (floats)
#define WS_STR  132                // padded Ws row stride (floats)
#define NOUT    (BATCH * OUT_DIM)  // 65536

// Scratch (device globals — no allocation in kernel_launch)
__device__ float        g_P[SPLITS * NOUT];  // split-K partials (4.2 MB)
__device__ unsigned int g_bar;               // monotonic barrier ticket counter

// ---------------------------------------------------------------------------
// f32x2 packed helpers (sm_103a FFMA2 — ptxas never emits this from C++)
// ---------------------------------------------------------------------------
__device__ __forceinline__ unsigned long long dup_f32x2(float v) {
    unsigned long long d;
    unsigned int u = __float_as_uint(v);
    asm("mov.b64 %0, {%1, %1};" : "=l"(d) : "r"(u));
    return d;
}
__device__ __forceinline__ void ffma2(unsigned long long& acc,
                                      unsigned long long a,
                                      unsigned long long b) {
    asm("fma.rn.f32x2 %0, %1, %2, %0;" : "+l"(acc) : "l"(a), "l"(b));
}

// ---------------------------------------------------------------------------
// Single persistent kernel, 512 threads (16 warps => 4/SMSP for latency hiding)
//   phase 1: build Fs/Ws in smem, f32x2 GEMM (4m x 4o per thread) -> partials
//   grid barrier (monotonic ticket; replay-safe)
//   phase 2: 65536 threads reduce the L2-warm partials -> out
// grid = (8, 16) = 128 blocks.
// ---------------------------------------------------------------------------
__global__ void __launch_bounds__(NTHR, 1)
fused_kernel(const float* __restrict__ x,
             const float* __restrict__ grid,
             const float* __restrict__ coef,
             const float* __restrict__ sb,
             const float* __restrict__ ss,
             const float* __restrict__ mask,
             float* __restrict__ out) {
    __shared__ float Fs[KC * FS_STR];   // 19.6 KB, [k][m] padded
    __shared__ float Ws[KC * WS_STR];   // 38.0 KB, [k][o] padded

    const int t  = threadIdx.x;
    const int m0 = blockIdx.x * BM;
    const int i0 = blockIdx.y * IPB;

    // ---- uniform extended knot vector (division-free) ----
    const float g0 = grid[0];
    const float g5 = grid[5];
    const float step = (g5 - g0) * 0.2f;
    const float inv1 = __frcp_rn(step);
    const float invr[3] = { inv1, 0.5f * inv1, inv1 * (1.0f / 3.0f) };

    float tk[12];
    tk[0]  = g0 - step * 3.0f;
    tk[1]  = g0 - step * 2.0f;
    tk[2]  = g0 - step;
    tk[3]  = g0;
    tk[4]  = grid[1];
    tk[5]  = grid[2];
    tk[6]  = grid[3];
    tk[7]  = grid[4];
    tk[8]  = g5;
    tk[9]  = g5 + step;
    tk[10] = g5 + step * 2.0f;
    tk[11] = g5 + step * 3.0f;

    // ---- Fs build: 64 n x 8 i = 512 x-values, 1 per thread ----
    {
        const int il = t & 7;
        const int nl = t >> 3;
        const float xv = __ldg(&x[(m0 + nl) * IN_DIM + i0 + il]);

        const float sig  = __frcp_rn(1.0f + __expf(-xv));
        const float silu = xv * sig;

        float B[11];
#pragma unroll
        for (int m = 0; m < 11; m++)
            B[m] = (xv >= tk[m] && xv < tk[m + 1]) ? 1.0f : 0.0f;
#pragma unroll
        for (int r = 1; r <= 3; r++) {
            const float iv = invr[r - 1];
#pragma unroll
            for (int m = 0; m < 11 - r; m++) {
                float alpha = (xv - tk[m]) * iv;
                float beta  = (tk[m + r + 1] - xv) * iv;
                B[m] = alpha * B[m] + beta * B[m + 1];
            }
        }

        const int kb = il * NFEAT;
        Fs[kb * FS_STR + nl] = silu;
#pragma unroll
        for (int j = 0; j < 8; j++)
            Fs[(kb + 1 + j) * FS_STR + nl] = B[j];
    }

    // ---- Ws build: 128 o x 8 i = 1024 (o,i) pairs, 2 per thread ----
#pragma unroll
    for (int q = 0; q < 2; q++) {
        const int p = t + NTHR * q;
        const int o = p >> 3;
        const int i = p & 7;
        const int s = o * IN_DIM + i0 + i;

        const float4 c0 = __ldg((const float4*)&coef[s * 8]);
        const float4 c1 = __ldg((const float4*)&coef[s * 8 + 4]);
        const float mk  = __ldg(&mask[s]);
        const float wb  = mk * __ldg(&sb[s]);
        const float ws  = mk * __ldg(&ss[s]);

        const int kb = i * NFEAT;
        Ws[kb * WS_STR + o]       = wb;
        Ws[(kb + 1) * WS_STR + o] = ws * c0.x;
        Ws[(kb + 2) * WS_STR + o] = ws * c0.y;
        Ws[(kb + 3) * WS_STR + o] = ws * c0.z;
        Ws[(kb + 4) * WS_STR + o] = ws * c0.w;
        Ws[(kb + 5) * WS_STR + o] = ws * c1.x;
        Ws[(kb + 6) * WS_STR + o] = ws * c1.y;
        Ws[(kb + 7) * WS_STR + o] = ws * c1.z;
        Ws[(kb + 8) * WS_STR + o] = ws * c1.w;
    }

    __syncthreads();

    // ---- GEMM: 4m x 4o per thread; f = warp-broadcast, w = 512B linear ----
    const int tm4 = (t >> 5) * 4;       // warp id * 4 : 0..60 (uniform in warp)
    const int to4 = (t & 31) * 4;       // lane * 4    : 0..124 (16B/lane linear)

    unsigned long long acc[4][2];       // 4 m-rows x 2 o-pairs
#pragma unroll
    for (int a = 0; a < 4; a++) { acc[a][0] = 0ULL; acc[a][1] = 0ULL; }

#pragma unroll 8
    for (int k = 0; k < KC; k++) {
        const float4 fa = *(const float4*)&Fs[k * FS_STR + tm4];       // bcast
        const ulonglong2 w = *(const ulonglong2*)&Ws[k * WS_STR + to4];// linear

        unsigned long long fd[4];
        fd[0] = dup_f32x2(fa.x); fd[1] = dup_f32x2(fa.y);
        fd[2] = dup_f32x2(fa.z); fd[3] = dup_f32x2(fa.w);

#pragma unroll
        for (int a = 0; a < 4; a++) {
            ffma2(acc[a][0], fd[a], w.x);
            ffma2(acc[a][1], fd[a], w.y);
        }
    }

    float* P = &g_P[blockIdx.y * NOUT];
#pragma unroll
    for (int a = 0; a < 4; a++) {
        const int row = m0 + tm4 + a;
        ulonglong2 v; v.x = acc[a][0]; v.y = acc[a][1];
        *(ulonglong2*)&P[row * OUT_DIM + to4] = v;   // 512B/warp linear
    }

    // ---- grid barrier (monotonic ticket; works across graph replays) ----
    __threadfence();
    __syncthreads();
    __shared__ unsigned int s_target;
    if (t == 0) {
        unsigned int ticket = atomicAdd(&g_bar, 1u);
        s_target = ticket - (ticket & (NBLK - 1)) + NBLK;  // epoch base + 128
    }
    __syncthreads();
    if (t == 0) {
        const unsigned int target = s_target;
        while (*(volatile unsigned int*)&g_bar < target) { }
    }
    __syncthreads();
    __threadfence();

    // ---- phase 2: reduce L2-warm partials, 1 output per thread ----
    const int flat = blockIdx.y * MT + blockIdx.x;   // 0..127
    const int idx  = flat * NTHR + t;                // 0..65535
    float v[SPLITS];
#pragma unroll
    for (int q = 0; q < SPLITS; q++)
        v[q] = g_P[q * NOUT + idx];
    float s = 0.0f;
#pragma unroll
    for (int q = 0; q < SPLITS; q++)
        s += v[q];
    out[idx] = s;
}

// ---------------------------------------------------------------------------
extern "C" void kernel_launch(void* const* d_in, const int* in_sizes, int n_in,
                              void* d_out, int out_size) {
    const float* x    = (const float*)d_in[0];
    const float* grid = (const float*)d_in[1];
    const float* coef = (const float*)d_in[2];
    const float* sb   = (const float*)d_in[3];
    const float* ss   = (const float*)d_in[4];
    const float* mask = (const float*)d_in[5];
    float* out = (float*)d_out;

    fused_kernel<<<dim3(MT, SPLITS), NTHR>>>(x, grid, coef, sb, ss, mask, out);
}